// round 2
// baseline (speedup 1.0000x reference)
#include <cuda_runtime.h>
#include <cuda_bf16.h>
#include <cstdint>

// Problem constants
#define BB 2
#define SS 4096
#define DD 512
#define HH 8
#define DQK 64
#define DV 64
#define WW 32
#define MROWS (BB * SS)   // 8192

// ---------------------------------------------------------------------------
// Scratch (no cudaMalloc allowed): q, k, v, attn_out each (B*S, 512) fp32
// ---------------------------------------------------------------------------
__device__ float g_q [MROWS * DD];
__device__ float g_k [MROWS * DD];
__device__ float g_v [MROWS * DD];
__device__ float g_ao[MROWS * DD];

// ---------------------------------------------------------------------------
// SGEMM (NT): C[M,N] = A[M,K] * B[N,K]^T, all row-major, fp32.
// M % 128 == 0, N % 128 == 0, K % 16 == 0 (all true here).
// 128x128 tile, BK=16, 256 threads, 8x8 per-thread microtile.
// ---------------------------------------------------------------------------
#define TILE_M 128
#define TILE_N 128
#define TILE_K 16

__global__ __launch_bounds__(256, 2)
void sgemm_nt(const float* __restrict__ A, const float* __restrict__ B,
              float* __restrict__ C, int M, int N, int K)
{
    __shared__ float As[TILE_K][TILE_M];
    __shared__ float Bs[TILE_K][TILE_N];

    const int tid = threadIdx.x;
    const int bm  = blockIdx.y * TILE_M;
    const int bn  = blockIdx.x * TILE_N;
    const int tr  = tid >> 4;          // 0..15  -> rows  tr*8 .. tr*8+7
    const int tc  = tid & 15;          // 0..15  -> cols  tc*8 .. tc*8+7

    const int lrow = tid >> 2;         // 0..63
    const int lc4  = (tid & 3) << 2;   // 0,4,8,12

    float acc[8][8];
    #pragma unroll
    for (int i = 0; i < 8; ++i)
        #pragma unroll
        for (int j = 0; j < 8; ++j) acc[i][j] = 0.f;

    for (int k0 = 0; k0 < K; k0 += TILE_K) {
        #pragma unroll
        for (int i = 0; i < 2; ++i) {
            int row = lrow + i * 64;
            float4 va = *(const float4*)(A + (size_t)(bm + row) * K + k0 + lc4);
            As[lc4 + 0][row] = va.x; As[lc4 + 1][row] = va.y;
            As[lc4 + 2][row] = va.z; As[lc4 + 3][row] = va.w;
            float4 vb = *(const float4*)(B + (size_t)(bn + row) * K + k0 + lc4);
            Bs[lc4 + 0][row] = vb.x; Bs[lc4 + 1][row] = vb.y;
            Bs[lc4 + 2][row] = vb.z; Bs[lc4 + 3][row] = vb.w;
        }
        __syncthreads();

        #pragma unroll
        for (int kk = 0; kk < TILE_K; ++kk) {
            float4 a0 = *(const float4*)&As[kk][tr * 8];
            float4 a1 = *(const float4*)&As[kk][tr * 8 + 4];
            float4 b0 = *(const float4*)&Bs[kk][tc * 8];
            float4 b1 = *(const float4*)&Bs[kk][tc * 8 + 4];
            float ra[8] = {a0.x, a0.y, a0.z, a0.w, a1.x, a1.y, a1.z, a1.w};
            float rb[8] = {b0.x, b0.y, b0.z, b0.w, b1.x, b1.y, b1.z, b1.w};
            #pragma unroll
            for (int i = 0; i < 8; ++i)
                #pragma unroll
                for (int j = 0; j < 8; ++j)
                    acc[i][j] = fmaf(ra[i], rb[j], acc[i][j]);
        }
        __syncthreads();
    }

    #pragma unroll
    for (int i = 0; i < 8; ++i) {
        float* cp = C + (size_t)(bm + tr * 8 + i) * N + bn + tc * 8;
        *(float4*)(cp)     = make_float4(acc[i][0], acc[i][1], acc[i][2], acc[i][3]);
        *(float4*)(cp + 4) = make_float4(acc[i][4], acc[i][5], acc[i][6], acc[i][7]);
    }
}

// ---------------------------------------------------------------------------
// Neighbor attention: one warp per (b, h, s).
//   lane w owns neighbor w for scoring/softmax;
//   lane l owns output dims 2l, 2l+1.
// q,k,v layout: row (b*S+s), col (h*64+d). out same layout.
// ---------------------------------------------------------------------------
__global__ __launch_bounds__(256)
void attn_kernel(const float* __restrict__ q, const float* __restrict__ k,
                 const float* __restrict__ v, const int* __restrict__ nb,
                 float* __restrict__ out)
{
    const unsigned wg   = (blockIdx.x * blockDim.x + threadIdx.x) >> 5;
    const int lane      = threadIdx.x & 31;
    const int s = wg & (SS - 1);
    const int h = (wg >> 12) & (HH - 1);
    const int b = wg >> 15;

    const size_t rowbase = ((size_t)b * SS) * DD;
    const float* qp = q + rowbase + (size_t)s * DD + h * DQK;
    const float2 qv = *(const float2*)(qp + lane * 2);

    const int myn = nb[s * WW + lane];   // lane w's neighbor index

    // ---- scores ----
    float my_score = 0.f;
    #pragma unroll
    for (int w = 0; w < WW; ++w) {
        int nw = __shfl_sync(0xffffffffu, myn, w);
        const float* kp = k + rowbase + (size_t)nw * DD + h * DQK;
        float2 kv = *(const float2*)(kp + lane * 2);
        float p = qv.x * kv.x + qv.y * kv.y;
        #pragma unroll
        for (int off = 16; off; off >>= 1)
            p += __shfl_xor_sync(0xffffffffu, p, off);
        if (lane == w) my_score = p;
    }
    my_score *= 0.125f;   // 1/sqrt(64)

    // ---- softmax across the 32 lanes ----
    float mx = my_score;
    #pragma unroll
    for (int off = 16; off; off >>= 1)
        mx = fmaxf(mx, __shfl_xor_sync(0xffffffffu, mx, off));
    float e = __expf(my_score - mx);
    float sum = e;
    #pragma unroll
    for (int off = 16; off; off >>= 1)
        sum += __shfl_xor_sync(0xffffffffu, sum, off);
    const float wgt = e / sum;

    // ---- weighted sum of V ----
    float2 acc = make_float2(0.f, 0.f);
    #pragma unroll
    for (int w = 0; w < WW; ++w) {
        int   nw = __shfl_sync(0xffffffffu, myn, w);
        float ww = __shfl_sync(0xffffffffu, wgt, w);
        const float* vp = v + rowbase + (size_t)nw * DD + h * DV;
        float2 vv = *(const float2*)(vp + lane * 2);
        acc.x = fmaf(ww, vv.x, acc.x);
        acc.y = fmaf(ww, vv.y, acc.y);
    }

    float* op = out + rowbase + (size_t)s * DD + h * DV;
    *(float2*)(op + lane * 2) = acc;
}

// ---------------------------------------------------------------------------
// Launch
// ---------------------------------------------------------------------------
extern "C" void kernel_launch(void* const* d_in, const int* in_sizes, int n_in,
                              void* d_out, int out_size)
{
    const float* x  = (const float*)d_in[0];
    const float* Wq = (const float*)d_in[1];
    const float* Wk = (const float*)d_in[2];
    const float* Wv = (const float*)d_in[3];
    const float* Wo = (const float*)d_in[4];
    const int*   nb = (const int*)  d_in[5];
    float* out = (float*)d_out;

    float *q, *k, *v, *ao;
    cudaGetSymbolAddress((void**)&q,  g_q);
    cudaGetSymbolAddress((void**)&k,  g_k);
    cudaGetSymbolAddress((void**)&v,  g_v);
    cudaGetSymbolAddress((void**)&ao, g_ao);

    dim3 gg(DD / TILE_N, MROWS / TILE_M);   // (4, 64) = 256 blocks

    sgemm_nt<<<gg, 256>>>(x,  Wq, q,  MROWS, DD, DD);
    sgemm_nt<<<gg, 256>>>(x,  Wk, k,  MROWS, DD, DD);
    sgemm_nt<<<gg, 256>>>(x,  Wv, v,  MROWS, DD, DD);

    // B*H*S = 65536 warps, 8 warps/block -> 8192 blocks
    attn_kernel<<<(BB * HH * SS) / 8, 256>>>(q, k, v, nb, ao);

    sgemm_nt<<<gg, 256>>>(ao, Wo, out, MROWS, DD, DD);
}

// round 3
// speedup vs baseline: 2.2313x; 2.2313x over previous
#include <cuda_runtime.h>
#include <cuda_bf16.h>
#include <cstdint>

// Problem constants
#define BB 2
#define SS 4096
#define DD 512
#define HH 8
#define DQK 64
#define DV 64
#define WW 32
#define MROWS (BB * SS)   // 8192

// Scratch: q, k, v, attn_out each (B*S, 512) fp32
__device__ float g_q [MROWS * DD];
__device__ float g_k [MROWS * DD];
__device__ float g_v [MROWS * DD];
__device__ float g_ao[MROWS * DD];

// ---------------------------------------------------------------------------
// TF32 tensor-core GEMM (NT): C[M,N] = A[M,K] * B[N,K]^T, row-major fp32.
// 128x128 tile, BK=16, 256 threads, 8 warps (2x4), warp tile 64x32,
// mma.m16n8k8 tf32, cp.async double buffering.
// smem layout: [row][k] with stride 20 floats (conflict-free fragment reads).
// ---------------------------------------------------------------------------
#define GBM 128
#define GBN 128
#define GBK 16
#define SSTR 20   // smem row stride in floats

__device__ __forceinline__ uint32_t f2tf32(float f) {
    uint32_t o;
    asm volatile("cvt.rna.tf32.f32 %0, %1;" : "=r"(o) : "f"(f));
    return o;
}

__device__ __forceinline__ void cp16(void* smem, const void* gmem) {
    uint32_t s = (uint32_t)__cvta_generic_to_shared(smem);
    asm volatile("cp.async.cg.shared.global [%0], [%1], 16;\n" :: "r"(s), "l"(gmem));
}
__device__ __forceinline__ void cp_commit() {
    asm volatile("cp.async.commit_group;\n");
}
template <int N> __device__ __forceinline__ void cp_wait() {
    asm volatile("cp.async.wait_group %0;\n" :: "n"(N));
}

__device__ __forceinline__ void mma_tf32(float c[4], uint32_t a[4], uint32_t b[2]) {
    asm volatile(
        "mma.sync.aligned.m16n8k8.row.col.f32.tf32.tf32.f32 "
        "{%0,%1,%2,%3}, {%4,%5,%6,%7}, {%8,%9}, {%0,%1,%2,%3};\n"
        : "+f"(c[0]), "+f"(c[1]), "+f"(c[2]), "+f"(c[3])
        : "r"(a[0]), "r"(a[1]), "r"(a[2]), "r"(a[3]), "r"(b[0]), "r"(b[1]));
}

__global__ __launch_bounds__(256, 1)
void tf32_gemm_nt(const float* __restrict__ A, const float* __restrict__ B,
                  float* __restrict__ C, int M, int N, int K)
{
    __shared__ float As[2][GBM * SSTR];
    __shared__ float Bs[2][GBN * SSTR];

    const int tid  = threadIdx.x;
    const int lane = tid & 31;
    const int warp = tid >> 5;
    const int bm   = blockIdx.y * GBM;
    const int bn   = blockIdx.x * GBN;
    const int wm   = (warp >> 2) * 64;   // warp row offset in tile
    const int wn   = (warp & 3) * 32;    // warp col offset in tile

    // global->smem load mapping: thread covers rows {row, row+64}, 4 floats at c4
    const int lrow = tid >> 2;           // 0..63
    const int lc4  = (tid & 3) << 2;     // 0,4,8,12

    const float* Ag = A + (size_t)(bm + lrow) * K + lc4;
    const float* Bg = B + (size_t)(bn + lrow) * K + lc4;

    float acc[4][4][4];
    #pragma unroll
    for (int mi = 0; mi < 4; ++mi)
        #pragma unroll
        for (int ni = 0; ni < 4; ++ni)
            #pragma unroll
            for (int r = 0; r < 4; ++r) acc[mi][ni][r] = 0.f;

    const int NIT = K / GBK;   // 32

    // prologue: stage 0
    {
        cp16(&As[0][lrow * SSTR + lc4],        Ag);
        cp16(&As[0][(lrow + 64) * SSTR + lc4], Ag + (size_t)64 * K);
        cp16(&Bs[0][lrow * SSTR + lc4],        Bg);
        cp16(&Bs[0][(lrow + 64) * SSTR + lc4], Bg + (size_t)64 * K);
        cp_commit();
    }

    const int qrow = lane >> 2;   // 0..7
    const int qcol = lane & 3;    // 0..3

    for (int it = 0; it < NIT; ++it) {
        const int buf = it & 1;
        if (it + 1 < NIT) {
            const int nb = (it + 1) & 1;
            const float* An = Ag + (it + 1) * GBK;
            const float* Bn = Bg + (it + 1) * GBK;
            cp16(&As[nb][lrow * SSTR + lc4],        An);
            cp16(&As[nb][(lrow + 64) * SSTR + lc4], An + (size_t)64 * K);
            cp16(&Bs[nb][lrow * SSTR + lc4],        Bn);
            cp16(&Bs[nb][(lrow + 64) * SSTR + lc4], Bn + (size_t)64 * K);
            cp_commit();
            cp_wait<1>();
        } else {
            cp_wait<0>();
        }
        __syncthreads();

        const float* as = As[buf];
        const float* bs = Bs[buf];

        #pragma unroll
        for (int kk = 0; kk < GBK; kk += 8) {
            uint32_t afr[4][4];
            #pragma unroll
            for (int mi = 0; mi < 4; ++mi) {
                const int r0 = (wm + mi * 16 + qrow) * SSTR + kk + qcol;
                afr[mi][0] = f2tf32(as[r0]);
                afr[mi][1] = f2tf32(as[r0 + 8 * SSTR]);
                afr[mi][2] = f2tf32(as[r0 + 4]);
                afr[mi][3] = f2tf32(as[r0 + 8 * SSTR + 4]);
            }
            uint32_t bfr[4][2];
            #pragma unroll
            for (int ni = 0; ni < 4; ++ni) {
                const int r0 = (wn + ni * 8 + qrow) * SSTR + kk + qcol;
                bfr[ni][0] = f2tf32(bs[r0]);
                bfr[ni][1] = f2tf32(bs[r0 + 4]);
            }
            #pragma unroll
            for (int mi = 0; mi < 4; ++mi)
                #pragma unroll
                for (int ni = 0; ni < 4; ++ni)
                    mma_tf32(acc[mi][ni], afr[mi], bfr[ni]);
        }
        __syncthreads();
    }

    // epilogue: c0,c1 -> (row, 2*qcol..+1); c2,c3 -> (row+8, ...)
    #pragma unroll
    for (int mi = 0; mi < 4; ++mi) {
        #pragma unroll
        for (int ni = 0; ni < 4; ++ni) {
            const int gr = bm + wm + mi * 16 + qrow;
            const int gc = bn + wn + ni * 8 + 2 * qcol;
            float* cp0 = C + (size_t)gr * N + gc;
            *(float2*)cp0 = make_float2(acc[mi][ni][0], acc[mi][ni][1]);
            *(float2*)(cp0 + (size_t)8 * N) = make_float2(acc[mi][ni][2], acc[mi][ni][3]);
        }
    }
}

// ---------------------------------------------------------------------------
// Neighbor attention: one warp per (b, h, s). (unchanged from R1)
// ---------------------------------------------------------------------------
__global__ __launch_bounds__(256)
void attn_kernel(const float* __restrict__ q, const float* __restrict__ k,
                 const float* __restrict__ v, const int* __restrict__ nb,
                 float* __restrict__ out)
{
    const unsigned wg   = (blockIdx.x * blockDim.x + threadIdx.x) >> 5;
    const int lane      = threadIdx.x & 31;
    const int s = wg & (SS - 1);
    const int h = (wg >> 12) & (HH - 1);
    const int b = wg >> 15;

    const size_t rowbase = ((size_t)b * SS) * DD;
    const float* qp = q + rowbase + (size_t)s * DD + h * DQK;
    const float2 qv = *(const float2*)(qp + lane * 2);

    const int myn = nb[s * WW + lane];

    float my_score = 0.f;
    #pragma unroll
    for (int w = 0; w < WW; ++w) {
        int nw = __shfl_sync(0xffffffffu, myn, w);
        const float* kp = k + rowbase + (size_t)nw * DD + h * DQK;
        float2 kv = *(const float2*)(kp + lane * 2);
        float p = qv.x * kv.x + qv.y * kv.y;
        #pragma unroll
        for (int off = 16; off; off >>= 1)
            p += __shfl_xor_sync(0xffffffffu, p, off);
        if (lane == w) my_score = p;
    }
    my_score *= 0.125f;

    float mx = my_score;
    #pragma unroll
    for (int off = 16; off; off >>= 1)
        mx = fmaxf(mx, __shfl_xor_sync(0xffffffffu, mx, off));
    float e = __expf(my_score - mx);
    float sum = e;
    #pragma unroll
    for (int off = 16; off; off >>= 1)
        sum += __shfl_xor_sync(0xffffffffu, sum, off);
    const float wgt = e / sum;

    float2 acc = make_float2(0.f, 0.f);
    #pragma unroll
    for (int w = 0; w < WW; ++w) {
        int   nw = __shfl_sync(0xffffffffu, myn, w);
        float ww = __shfl_sync(0xffffffffu, wgt, w);
        const float* vp = v + rowbase + (size_t)nw * DD + h * DV;
        float2 vv = *(const float2*)(vp + lane * 2);
        acc.x = fmaf(ww, vv.x, acc.x);
        acc.y = fmaf(ww, vv.y, acc.y);
    }

    float* op = out + rowbase + (size_t)s * DD + h * DV;
    *(float2*)(op + lane * 2) = acc;
}

// ---------------------------------------------------------------------------
// Launch
// ---------------------------------------------------------------------------
extern "C" void kernel_launch(void* const* d_in, const int* in_sizes, int n_in,
                              void* d_out, int out_size)
{
    const float* x  = (const float*)d_in[0];
    const float* Wq = (const float*)d_in[1];
    const float* Wk = (const float*)d_in[2];
    const float* Wv = (const float*)d_in[3];
    const float* Wo = (const float*)d_in[4];
    const int*   nb = (const int*)  d_in[5];
    float* out = (float*)d_out;

    float *q, *k, *v, *ao;
    cudaGetSymbolAddress((void**)&q,  g_q);
    cudaGetSymbolAddress((void**)&k,  g_k);
    cudaGetSymbolAddress((void**)&v,  g_v);
    cudaGetSymbolAddress((void**)&ao, g_ao);

    dim3 gg(DD / GBN, MROWS / GBM);   // (4, 64) = 256 blocks

    tf32_gemm_nt<<<gg, 256>>>(x,  Wq, q,  MROWS, DD, DD);
    tf32_gemm_nt<<<gg, 256>>>(x,  Wk, k,  MROWS, DD, DD);
    tf32_gemm_nt<<<gg, 256>>>(x,  Wv, v,  MROWS, DD, DD);

    attn_kernel<<<(BB * HH * SS) / 8, 256>>>(q, k, v, nb, ao);

    tf32_gemm_nt<<<gg, 256>>>(ao, Wo, out, MROWS, DD, DD);
}